// round 16
// baseline (speedup 1.0000x reference)
#include <cuda_runtime.h>
#include <math.h>

#define NB    32
#define NF    500
#define FEAT  256
#define COUT  2
#define CIN   2
#define KK    16
#define FRAME 160
#define OVL   40
#define NSAMP (NF * FRAME)          // 80000
#define NFILT (COUT * CIN * KK)     // 64

#define GAIN_A 0.69077552789821368f
#define SG     0.50118723362727224f
#define OMSG   0.49881276637272776f

// Per-frame filters: [(b*NF+f)*64 + cout*32 + cin*16 + k]
__device__ float g_w[(size_t)NB * NF * NFILT];

// ===========================================================================
// Kernel A: filter synthesis GEMM + epilogue (R12 version, verbatim, plus a
// block-offset parameter for chunked launches).
// ===========================================================================
#define TBF 128
#define FSTRIDE4 65
#define WSTRIDE  68

__global__ void __launch_bounds__(256) filt_kernel(
    const float* __restrict__ feat,
    const float* __restrict__ ckw,
    const float* __restrict__ ckb,
    const float* __restrict__ fgw,
    const float* __restrict__ fgb,
    int blk0)
{
    extern __shared__ float sm[];
    float*  fs   = sm;                                   // [128][260]
    float*  Wt   = sm + TBF * 260;                       // [256][68]
    float*  gg   = Wt + 256 * WSTRIDE;
    float*  invn = gg + TBF * 2;
    float*  gain = invn + TBF * 2;
    float4* fs4  = (float4*)fs;
    float4* Wt4  = (float4*)Wt;

    int tid = threadIdx.x;
    int bf0 = (blk0 + blockIdx.x) * TBF;

    const float4* feat4 = (const float4*)feat;
    for (int i = tid; i < TBF * 64; i += 256) {
        int r = i >> 6, c4 = i & 63;
        fs4[r * FSTRIDE4 + c4] = feat4[(size_t)(bf0 + r) * 64 + c4];
    }
    for (int i = tid; i < 64 * 256; i += 256) {
        int o = i >> 8, fe = i & 255;
        Wt[fe * WSTRIDE + o] = ckw[i];
    }
    {
        int fe = tid;
        Wt[fe * WSTRIDE + 64] = 0.f; Wt[fe * WSTRIDE + 65] = 0.f;
        Wt[fe * WSTRIDE + 66] = 0.f; Wt[fe * WSTRIDE + 67] = 0.f;
    }
    __syncthreads();

    int ogrp = tid & 15;
    int rgrp = tid >> 4;
    int o0 = ogrp * 4;
    int r0 = rgrp * 8;

    float acc[8][4];
    #pragma unroll
    for (int i = 0; i < 8; ++i)
        #pragma unroll
        for (int j = 0; j < 4; ++j) acc[i][j] = 0.f;

    const float4* fsp = fs4 + r0 * FSTRIDE4;
    const float4* wtp = Wt4 + ogrp;

    #pragma unroll 4
    for (int fe4 = 0; fe4 < 64; ++fe4) {
        float4 fv[8];
        #pragma unroll
        for (int i = 0; i < 8; ++i) fv[i] = fsp[i * FSTRIDE4 + fe4];
        float4 w0 = wtp[(4 * fe4 + 0) * 17];
        float4 w1 = wtp[(4 * fe4 + 1) * 17];
        float4 w2 = wtp[(4 * fe4 + 2) * 17];
        float4 w3 = wtp[(4 * fe4 + 3) * 17];
        #pragma unroll
        for (int i = 0; i < 8; ++i) {
            acc[i][0] = fmaf(fv[i].x, w0.x, acc[i][0]);
            acc[i][1] = fmaf(fv[i].x, w0.y, acc[i][1]);
            acc[i][2] = fmaf(fv[i].x, w0.z, acc[i][2]);
            acc[i][3] = fmaf(fv[i].x, w0.w, acc[i][3]);
            acc[i][0] = fmaf(fv[i].y, w1.x, acc[i][0]);
            acc[i][1] = fmaf(fv[i].y, w1.y, acc[i][1]);
            acc[i][2] = fmaf(fv[i].y, w1.z, acc[i][2]);
            acc[i][3] = fmaf(fv[i].y, w1.w, acc[i][3]);
            acc[i][0] = fmaf(fv[i].z, w2.x, acc[i][0]);
            acc[i][1] = fmaf(fv[i].z, w2.y, acc[i][1]);
            acc[i][2] = fmaf(fv[i].z, w2.z, acc[i][2]);
            acc[i][3] = fmaf(fv[i].z, w2.w, acc[i][3]);
            acc[i][0] = fmaf(fv[i].w, w3.x, acc[i][0]);
            acc[i][1] = fmaf(fv[i].w, w3.y, acc[i][1]);
            acc[i][2] = fmaf(fv[i].w, w3.z, acc[i][2]);
            acc[i][3] = fmaf(fv[i].w, w3.w, acc[i][3]);
        }
    }

    {
        int r = tid >> 1, c = tid & 1;
        const float4* fr = fs4 + r * FSTRIDE4;
        const float4* gw = (const float4*)fgw + c * 64;
        float s = 0.f;
        #pragma unroll 4
        for (int fe4 = 0; fe4 < 64; ++fe4) {
            float4 a = fr[fe4];
            float4 b = __ldg(&gw[fe4]);
            s += a.x * b.x + a.y * b.y + a.z * b.z + a.w * b.w;
        }
        gg[r * 2 + c] = s + __ldg(&fgb[c]);
    }
    __syncthreads();

    float* raw = fs;
    #pragma unroll
    for (int i = 0; i < 8; ++i)
        #pragma unroll
        for (int j = 0; j < 4; ++j)
            raw[(r0 + i) * WSTRIDE + (o0 + j)] = acc[i][j] + __ldg(&ckb[o0 + j]);
    __syncthreads();

    {
        int r = tid >> 1, c = tid & 1;
        float ss = 0.f;
        #pragma unroll
        for (int i = 0; i < 32; ++i) {
            float v = raw[r * WSTRIDE + c * 32 + i];
            ss += v * v;
        }
        invn[r * 2 + c] = 1.0f / (1e-6f + sqrtf(ss));
        gain[r * 2 + c] = expf(GAIN_A * tanhf(gg[r * 2 + c]));
    }
    __syncthreads();

    for (int idx = tid; idx < TBF * NFILT; idx += 256) {
        int r = idx >> 6, o = idx & 63;
        int co = o >> 5;
        float v = SG * raw[r * WSTRIDE + o] * invn[r * 2 + co];
        if ((o & 15) == 7) v += OMSG;
        g_w[(size_t)(bf0 + r) * NFILT + o] = v * gain[r * 2 + co];
    }
}

// ===========================================================================
// Kernel B: R12 conv (best known, 25.9us), verbatim, plus batch offset.
// ===========================================================================
#define FPB  4
#define XROW 176

__global__ void __launch_bounds__(128, 9) conv_kernel(
    const float* __restrict__ x,     // (B, CIN, NSAMP)
    const float* __restrict__ owin,  // (40,)
    float* __restrict__ out,         // (B, COUT, NSAMP)
    int b0)
{
    __shared__ __align__(16) float xs[CIN][FPB * XROW];
    __shared__ __align__(16) float wsm[(FPB + 1) * 68];
    __shared__ __align__(16) float ob[FPB][COUT][FRAME];
    __shared__ float w1s[OVL], w2s[OVL];

    const int NT = 128;
    int f0 = blockIdx.x * FPB;
    int b  = b0 + blockIdx.y;
    int tid  = threadIdx.x;
    int lane = tid & 31;
    int w    = tid >> 5;

    const float* xb = x + (size_t)b * CIN * NSAMP;
    for (int i = tid; i < CIN * FPB * 44; i += NT) {
        int ci  = i / (FPB * 44);
        int rem = i - ci * (FPB * 44);
        int f   = rem / 44, q = rem - f * 44;
        int gb  = (f0 + f) * FRAME - 16 + q * 4;
        float4 v = make_float4(0.f, 0.f, 0.f, 0.f);
        if (gb >= 0)
            v = *(const float4*)(xb + (size_t)ci * NSAMP + gb);
        *(float4*)&xs[ci][f * XROW + q * 4] = v;
    }
    for (int i = tid; i < (FPB + 1) * 64; i += NT) {
        int fr = i >> 6, o = i & 63;
        int fi = f0 - 1 + fr;
        wsm[fr * 68 + o] = (fi >= 0)
            ? g_w[((size_t)b * NF + fi) * NFILT + o] : 0.f;
    }
    if (tid < OVL) {
        w2s[tid] = owin[tid];
        w1s[tid] = owin[OVL - 1 - tid];
    }
    __syncthreads();

    int p   = w >> 1, jh = w & 1;
    int l16 = lane & 15, fsel = lane >> 4;
    int fl  = 2 * p + fsel;
    int j0  = jh * 80 + 5 * l16;
    int xbase = fl * XROW + 1 + j0;

    float a0[5] = {0,0,0,0,0}, a1[5] = {0,0,0,0,0};
    float p0[5] = {0,0,0,0,0}, p1[5] = {0,0,0,0,0};

    const float4* wc = (const float4*)(wsm + (fl + 1) * 68);
    const float4* wp = (const float4*)(wsm + fl * 68);
    bool tail = (j0 < OVL);

    #pragma unroll
    for (int ci = 0; ci < CIN; ++ci) {
        float xw[20];
        #pragma unroll
        for (int i = 0; i < 20; ++i)
            xw[i] = xs[ci][xbase + i];

        #pragma unroll
        for (int kc = 0; kc < 4; ++kc) {
            float4 c0 = wc[ci * 4 + kc];
            float4 c1 = wc[8 + ci * 4 + kc];
            float wk0[4] = {c0.x, c0.y, c0.z, c0.w};
            float wk1[4] = {c1.x, c1.y, c1.z, c1.w};
            #pragma unroll
            for (int kk = 0; kk < 4; ++kk) {
                int k = 4 * kc + kk;
                #pragma unroll
                for (int m = 0; m < 5; ++m) {
                    float xv = xw[m + 15 - k];
                    a0[m] = fmaf(wk0[kk], xv, a0[m]);
                    a1[m] = fmaf(wk1[kk], xv, a1[m]);
                }
            }
        }
        if (tail) {
            #pragma unroll
            for (int kc = 0; kc < 4; ++kc) {
                float4 c0 = wp[ci * 4 + kc];
                float4 c1 = wp[8 + ci * 4 + kc];
                float wk0[4] = {c0.x, c0.y, c0.z, c0.w};
                float wk1[4] = {c1.x, c1.y, c1.z, c1.w};
                #pragma unroll
                for (int kk = 0; kk < 4; ++kk) {
                    int k = 4 * kc + kk;
                    #pragma unroll
                    for (int m = 0; m < 5; ++m) {
                        float xv = xw[m + 15 - k];
                        p0[m] = fmaf(wk0[kk], xv, p0[m]);
                        p1[m] = fmaf(wk1[kk], xv, p1[m]);
                    }
                }
            }
        }
    }

    if (tail) {
        #pragma unroll
        for (int m = 0; m < 5; ++m) {
            int j = j0 + m;
            ob[fl][0][j] = w1s[j] * a0[m] + w2s[j] * p0[m];
            ob[fl][1][j] = w1s[j] * a1[m] + w2s[j] * p1[m];
        }
    } else {
        #pragma unroll
        for (int m = 0; m < 5; ++m) {
            int j = j0 + m;
            ob[fl][0][j] = a0[m];
            ob[fl][1][j] = a1[m];
        }
    }
    __syncthreads();

    int f = f0 + w;
    #pragma unroll
    for (int co = 0; co < COUT; ++co) {
        float4* op = (float4*)(out + (size_t)b * COUT * NSAMP
                               + (size_t)co * NSAMP + (size_t)f * FRAME);
        const float4* obp = (const float4*)ob[w][co];
        #pragma unroll
        for (int i = lane; i < FRAME / 4; i += 32)
            op[i] = obp[i];
    }
}

// ===========================================================================
// Launch: 4-chunk batch pipeline across two streams (fork/join via events).
// filt chunk k (32 blocks, boundary blocks redundantly recomputed) covers all
// filter rows needed by conv chunk k (8 batches).
// ===========================================================================
#define NCHUNK 4

extern "C" void kernel_launch(void* const* d_in, const int* in_sizes, int n_in,
                              void* d_out, int out_size)
{
    const float* x    = (const float*)d_in[0];
    const float* feat = (const float*)d_in[1];
    const float* ckw  = (const float*)d_in[2];
    const float* ckb  = (const float*)d_in[3];
    const float* fgw  = (const float*)d_in[4];
    const float* fgb  = (const float*)d_in[5];
    const float* ow   = (const float*)d_in[6];
    float* out = (float*)d_out;

    int smem = (TBF * 260 + 256 * WSTRIDE + 3 * TBF * 2) * (int)sizeof(float);

    static int configured = 0;
    static cudaStream_t s2;
    static cudaEvent_t ev[NCHUNK], ejoin;
    if (!configured) {
        cudaFuncSetAttribute(filt_kernel,
                             cudaFuncAttributeMaxDynamicSharedMemorySize, smem);
        cudaStreamCreateWithFlags(&s2, cudaStreamNonBlocking);
        for (int k = 0; k < NCHUNK; ++k)
            cudaEventCreateWithFlags(&ev[k], cudaEventDisableTiming);
        cudaEventCreateWithFlags(&ejoin, cudaEventDisableTiming);
        configured = 1;
    }

    // filt chunk k: blocks [31k, 31k+32) -> rows [3968k, 3968k+4096)
    // covers conv chunk k rows [4000k, 4000k+4000) combined with chunks <k.
    for (int k = 0; k < NCHUNK; ++k) {
        filt_kernel<<<32, 256, smem>>>(feat, ckw, ckb, fgw, fgb, 31 * k);
        cudaEventRecord(ev[k], 0);
    }
    for (int k = 0; k < NCHUNK; ++k) {
        cudaStreamWaitEvent(s2, ev[k], 0);
        conv_kernel<<<dim3(NF / FPB, NB / NCHUNK), 128, 0, s2>>>(
            x, ow, out, k * (NB / NCHUNK));
    }
    cudaEventRecord(ejoin, s2);
    cudaStreamWaitEvent(0, ejoin, 0);
}

// round 17
// speedup vs baseline: 2.3657x; 2.3657x over previous
#include <cuda_runtime.h>
#include <math.h>

#define NB    32
#define NF    500
#define FEAT  256
#define COUT  2
#define CIN   2
#define KK    16
#define FRAME 160
#define OVL   40
#define NSAMP (NF * FRAME)          // 80000
#define NFILT (COUT * CIN * KK)     // 64
#define NROWS (NB * NF)             // 16000

#define GAIN_A 0.69077552789821368f
#define SG     0.50118723362727224f
#define OMSG   0.49881276637272776f

// Per-frame filters: [(b*NF+f)*64 + cout*32 + cin*16 + k]
__device__ float g_w[(size_t)NB * NF * NFILT];

// ===========================================================================
// Kernel A: filter synthesis GEMM + epilogue.
// TBF=112 rows/block (thread tile 7x4), 143 blocks -> one wave on 148 SMs,
// per-block FMA critical path 28.7K cyc (~16us) vs 32.8K at TBF=128.
// Boundary block clamps loads and guards stores.
// ===========================================================================
#define TBF 112
#define FSTRIDE4 65
#define WSTRIDE  68
#define NFBLK ((NROWS + TBF - 1) / TBF)   // 143

__global__ void __launch_bounds__(256) filt_kernel(
    const float* __restrict__ feat,
    const float* __restrict__ ckw,
    const float* __restrict__ ckb,
    const float* __restrict__ fgw,
    const float* __restrict__ fgb)
{
    extern __shared__ float sm[];
    float*  fs   = sm;                                   // [112][260]
    float*  Wt   = sm + TBF * 260;                       // [256][68]
    float*  gg   = Wt + 256 * WSTRIDE;
    float*  invn = gg + TBF * 2;
    float*  gain = invn + TBF * 2;
    float4* fs4  = (float4*)fs;
    float4* Wt4  = (float4*)Wt;

    int tid = threadIdx.x;
    int bf0 = blockIdx.x * TBF;

    const float4* feat4 = (const float4*)feat;
    for (int i = tid; i < TBF * 64; i += 256) {
        int r = i >> 6, c4 = i & 63;
        int rr = bf0 + r; if (rr >= NROWS) rr = NROWS - 1;   // clamp
        fs4[r * FSTRIDE4 + c4] = feat4[(size_t)rr * 64 + c4];
    }
    for (int i = tid; i < 64 * 256; i += 256) {
        int o = i >> 8, fe = i & 255;
        Wt[fe * WSTRIDE + o] = ckw[i];
    }
    {
        int fe = tid;
        Wt[fe * WSTRIDE + 64] = 0.f; Wt[fe * WSTRIDE + 65] = 0.f;
        Wt[fe * WSTRIDE + 66] = 0.f; Wt[fe * WSTRIDE + 67] = 0.f;
    }
    __syncthreads();

    int ogrp = tid & 15;
    int rgrp = tid >> 4;
    int o0 = ogrp * 4;
    int r0 = rgrp * 7;                // 16 groups x 7 rows = 112

    float acc[7][4];
    #pragma unroll
    for (int i = 0; i < 7; ++i)
        #pragma unroll
        for (int j = 0; j < 4; ++j) acc[i][j] = 0.f;

    const float4* fsp = fs4 + r0 * FSTRIDE4;
    const float4* wtp = Wt4 + ogrp;

    #pragma unroll 4
    for (int fe4 = 0; fe4 < 64; ++fe4) {
        float4 fv[7];
        #pragma unroll
        for (int i = 0; i < 7; ++i) fv[i] = fsp[i * FSTRIDE4 + fe4];
        float4 w0 = wtp[(4 * fe4 + 0) * 17];
        float4 w1 = wtp[(4 * fe4 + 1) * 17];
        float4 w2 = wtp[(4 * fe4 + 2) * 17];
        float4 w3 = wtp[(4 * fe4 + 3) * 17];
        #pragma unroll
        for (int i = 0; i < 7; ++i) {
            acc[i][0] = fmaf(fv[i].x, w0.x, acc[i][0]);
            acc[i][1] = fmaf(fv[i].x, w0.y, acc[i][1]);
            acc[i][2] = fmaf(fv[i].x, w0.z, acc[i][2]);
            acc[i][3] = fmaf(fv[i].x, w0.w, acc[i][3]);
            acc[i][0] = fmaf(fv[i].y, w1.x, acc[i][0]);
            acc[i][1] = fmaf(fv[i].y, w1.y, acc[i][1]);
            acc[i][2] = fmaf(fv[i].y, w1.z, acc[i][2]);
            acc[i][3] = fmaf(fv[i].y, w1.w, acc[i][3]);
            acc[i][0] = fmaf(fv[i].z, w2.x, acc[i][0]);
            acc[i][1] = fmaf(fv[i].z, w2.y, acc[i][1]);
            acc[i][2] = fmaf(fv[i].z, w2.z, acc[i][2]);
            acc[i][3] = fmaf(fv[i].z, w2.w, acc[i][3]);
            acc[i][0] = fmaf(fv[i].w, w3.x, acc[i][0]);
            acc[i][1] = fmaf(fv[i].w, w3.y, acc[i][1]);
            acc[i][2] = fmaf(fv[i].w, w3.z, acc[i][2]);
            acc[i][3] = fmaf(fv[i].w, w3.w, acc[i][3]);
        }
    }

    // ---- gain logits: threads 0..223 -> (row tid>>1, cout tid&1) ----
    if (tid < TBF * 2) {
        int r = tid >> 1, c = tid & 1;
        const float4* fr = fs4 + r * FSTRIDE4;
        const float4* gw = (const float4*)fgw + c * 64;
        float s = 0.f;
        #pragma unroll 4
        for (int fe4 = 0; fe4 < 64; ++fe4) {
            float4 a = fr[fe4];
            float4 b = __ldg(&gw[fe4]);
            s += a.x * b.x + a.y * b.y + a.z * b.z + a.w * b.w;
        }
        gg[tid] = s + __ldg(&fgb[c]);
    }
    __syncthreads();

    float* raw = fs;                  // reuse fs region, stride 68
    #pragma unroll
    for (int i = 0; i < 7; ++i)
        #pragma unroll
        for (int j = 0; j < 4; ++j)
            raw[(r0 + i) * WSTRIDE + (o0 + j)] = acc[i][j] + __ldg(&ckb[o0 + j]);
    __syncthreads();

    if (tid < TBF * 2) {
        int r = tid >> 1, c = tid & 1;
        float ss = 0.f;
        #pragma unroll
        for (int i = 0; i < 32; ++i) {
            float v = raw[r * WSTRIDE + c * 32 + i];
            ss += v * v;
        }
        invn[tid] = 1.0f / (1e-6f + sqrtf(ss));
        gain[tid] = expf(GAIN_A * tanhf(gg[tid]));
    }
    __syncthreads();

    for (int idx = tid; idx < TBF * NFILT; idx += 256) {
        int r = idx >> 6, o = idx & 63;
        if (bf0 + r >= NROWS) break;                    // boundary guard
        int co = o >> 5;
        float v = SG * raw[r * WSTRIDE + o] * invn[r * 2 + co];
        if ((o & 15) == 7) v += OMSG;
        g_w[(size_t)(bf0 + r) * NFILT + o] = v * gain[r * 2 + co];
    }
}

// ===========================================================================
// Kernel B: R12 conv (best known, 25.9us) — verbatim.
// Warp = half-frame ranges of a frame pair; consolidated predicated tail.
// ===========================================================================
#define FPB  4
#define XROW 176

__global__ void __launch_bounds__(128, 9) conv_kernel(
    const float* __restrict__ x,     // (B, CIN, NSAMP)
    const float* __restrict__ owin,  // (40,)
    float* __restrict__ out)         // (B, COUT, NSAMP)
{
    __shared__ __align__(16) float xs[CIN][FPB * XROW];
    __shared__ __align__(16) float wsm[(FPB + 1) * 68];
    __shared__ __align__(16) float ob[FPB][COUT][FRAME];
    __shared__ float w1s[OVL], w2s[OVL];

    const int NT = 128;
    int f0 = blockIdx.x * FPB;
    int b  = blockIdx.y;
    int tid  = threadIdx.x;
    int lane = tid & 31;
    int w    = tid >> 5;

    const float* xb = x + (size_t)b * CIN * NSAMP;
    for (int i = tid; i < CIN * FPB * 44; i += NT) {
        int ci  = i / (FPB * 44);
        int rem = i - ci * (FPB * 44);
        int f   = rem / 44, q = rem - f * 44;
        int gb  = (f0 + f) * FRAME - 16 + q * 4;
        float4 v = make_float4(0.f, 0.f, 0.f, 0.f);
        if (gb >= 0)
            v = *(const float4*)(xb + (size_t)ci * NSAMP + gb);
        *(float4*)&xs[ci][f * XROW + q * 4] = v;
    }
    for (int i = tid; i < (FPB + 1) * 64; i += NT) {
        int fr = i >> 6, o = i & 63;
        int fi = f0 - 1 + fr;
        wsm[fr * 68 + o] = (fi >= 0)
            ? g_w[((size_t)b * NF + fi) * NFILT + o] : 0.f;
    }
    if (tid < OVL) {
        w2s[tid] = owin[tid];
        w1s[tid] = owin[OVL - 1 - tid];
    }
    __syncthreads();

    int p   = w >> 1, jh = w & 1;
    int l16 = lane & 15, fsel = lane >> 4;
    int fl  = 2 * p + fsel;
    int j0  = jh * 80 + 5 * l16;
    int xbase = fl * XROW + 1 + j0;

    float a0[5] = {0,0,0,0,0}, a1[5] = {0,0,0,0,0};
    float p0[5] = {0,0,0,0,0}, p1[5] = {0,0,0,0,0};

    const float4* wc = (const float4*)(wsm + (fl + 1) * 68);
    const float4* wp = (const float4*)(wsm + fl * 68);
    bool tail = (j0 < OVL);

    #pragma unroll
    for (int ci = 0; ci < CIN; ++ci) {
        float xw[20];
        #pragma unroll
        for (int i = 0; i < 20; ++i)
            xw[i] = xs[ci][xbase + i];

        #pragma unroll
        for (int kc = 0; kc < 4; ++kc) {
            float4 c0 = wc[ci * 4 + kc];
            float4 c1 = wc[8 + ci * 4 + kc];
            float wk0[4] = {c0.x, c0.y, c0.z, c0.w};
            float wk1[4] = {c1.x, c1.y, c1.z, c1.w};
            #pragma unroll
            for (int kk = 0; kk < 4; ++kk) {
                int k = 4 * kc + kk;
                #pragma unroll
                for (int m = 0; m < 5; ++m) {
                    float xv = xw[m + 15 - k];
                    a0[m] = fmaf(wk0[kk], xv, a0[m]);
                    a1[m] = fmaf(wk1[kk], xv, a1[m]);
                }
            }
        }
        if (tail) {
            #pragma unroll
            for (int kc = 0; kc < 4; ++kc) {
                float4 c0 = wp[ci * 4 + kc];
                float4 c1 = wp[8 + ci * 4 + kc];
                float wk0[4] = {c0.x, c0.y, c0.z, c0.w};
                float wk1[4] = {c1.x, c1.y, c1.z, c1.w};
                #pragma unroll
                for (int kk = 0; kk < 4; ++kk) {
                    int k = 4 * kc + kk;
                    #pragma unroll
                    for (int m = 0; m < 5; ++m) {
                        float xv = xw[m + 15 - k];
                        p0[m] = fmaf(wk0[kk], xv, p0[m]);
                        p1[m] = fmaf(wk1[kk], xv, p1[m]);
                    }
                }
            }
        }
    }

    if (tail) {
        #pragma unroll
        for (int m = 0; m < 5; ++m) {
            int j = j0 + m;
            ob[fl][0][j] = w1s[j] * a0[m] + w2s[j] * p0[m];
            ob[fl][1][j] = w1s[j] * a1[m] + w2s[j] * p1[m];
        }
    } else {
        #pragma unroll
        for (int m = 0; m < 5; ++m) {
            int j = j0 + m;
            ob[fl][0][j] = a0[m];
            ob[fl][1][j] = a1[m];
        }
    }
    __syncthreads();

    int f = f0 + w;
    #pragma unroll
    for (int co = 0; co < COUT; ++co) {
        float4* op = (float4*)(out + (size_t)b * COUT * NSAMP
                               + (size_t)co * NSAMP + (size_t)f * FRAME);
        const float4* obp = (const float4*)ob[w][co];
        #pragma unroll
        for (int i = lane; i < FRAME / 4; i += 32)
            op[i] = obp[i];
    }
}

extern "C" void kernel_launch(void* const* d_in, const int* in_sizes, int n_in,
                              void* d_out, int out_size)
{
    const float* x    = (const float*)d_in[0];
    const float* feat = (const float*)d_in[1];
    const float* ckw  = (const float*)d_in[2];
    const float* ckb  = (const float*)d_in[3];
    const float* fgw  = (const float*)d_in[4];
    const float* fgb  = (const float*)d_in[5];
    const float* ow   = (const float*)d_in[6];
    float* out = (float*)d_out;

    int smem = (TBF * 260 + 256 * WSTRIDE + 3 * TBF * 2) * (int)sizeof(float);
    static int configured = 0;
    if (!configured) {
        cudaFuncSetAttribute(filt_kernel,
                             cudaFuncAttributeMaxDynamicSharedMemorySize, smem);
        configured = 1;
    }

    filt_kernel<<<NFBLK, 256, smem>>>(feat, ckw, ckb, fgw, fgb);
    conv_kernel<<<dim3(NF / FPB, NB), 128>>>(x, ow, out);
}